// round 11
// baseline (speedup 1.0000x reference)
#include <cuda_runtime.h>

// EdgeNet v11: phase-1 identical to R10 (7.19 TB/s, atomic nonzero flush into
// 1 MB accumulator). Phase-2: 8 lanes/edge (halved serial MLP chain), warp
// handles 4 edges, smem weight transpose + shfl combine.

#define N_NODES 8192
#define N_EDGES 32768
#define S_SEG   16
#define NODES_PER_SEG (N_NODES / S_SEG)      // 512
#define E4      (N_EDGES / 4)                // 8192 float4 columns
#define A_THREADS 256
#define EGRPS   (E4 / A_THREADS)             // 32 edge-group blocks
#define NHID    100
#define M_THREADS 256

// Direct accumulator: [edge][8] floats (bo.xyzw, bi.xyzw).  1 MB.
// BSS zero-init covers the first run; phase-2 re-zeroes after consuming.
__device__ float g_accum[(size_t)N_EDGES * 8];

__device__ __forceinline__ void fma4(float4& a, float s, const float4& x) {
    a.x = fmaf(s, x.x, a.x);
    a.y = fmaf(s, x.y, a.y);
    a.z = fmaf(s, x.z, a.z);
    a.w = fmaf(s, x.w, a.w);
}
__device__ __forceinline__ float fast_tanh(float x) {
    float e = __expf(2.0f * x);
    return 1.0f - __fdividef(2.0f, e + 1.0f);
}

__device__ __forceinline__ void flush_nz(const float4& v, int e, int half) {
    // Skip all-zero partials (exact: adding zero is a no-op; each (edge,side)
    // has exactly one nonzero segment, landing on a zeroed slot).
    if (v.x != 0.0f || v.y != 0.0f || v.z != 0.0f || v.w != 0.0f) {
        float* a = &g_accum[(size_t)e * 8 + half * 4];
        atomicAdd(a + 0, v.x);
        atomicAdd(a + 1, v.y);
        atomicAdd(a + 2, v.z);
        atomicAdd(a + 3, v.w);
    }
}

__global__ __launch_bounds__(A_THREADS, 4)
void edgenet_accum_kernel(const float* __restrict__ X,
                          const float* __restrict__ Ri,
                          const float* __restrict__ Ro)
{
    __shared__ float4 sX[NODES_PER_SEG];   // 8 KB

    const int tid = threadIdx.x;
    const int seg = blockIdx.y;
    const int n0  = seg * NODES_PER_SEG;

    const float4* __restrict__ X4 = (const float4*)X;
    for (int i = tid; i < NODES_PER_SEG; i += A_THREADS)
        sX[i] = X4[n0 + i];
    __syncthreads();

    const int e4 = blockIdx.x * A_THREADS + tid;
    const float4* __restrict__ ro_p = (const float4*)Ro + (size_t)n0 * E4 + e4;
    const float4* __restrict__ ri_p = (const float4*)Ri + (size_t)n0 * E4 + e4;

    float4 ao0 = {0,0,0,0}, ao1 = {0,0,0,0}, ao2 = {0,0,0,0}, ao3 = {0,0,0,0};
    float4 ai0 = {0,0,0,0}, ai1 = {0,0,0,0}, ai2 = {0,0,0,0}, ai3 = {0,0,0,0};

    #pragma unroll 4
    for (int n = 0; n < NODES_PER_SEG; ++n) {
        const float4 ro = __ldcs(&ro_p[(size_t)n * E4]);   // stream-once
        const float4 ri = __ldcs(&ri_p[(size_t)n * E4]);
        const float4 x  = sX[n];
        fma4(ao0, ro.x, x);  fma4(ao1, ro.y, x);
        fma4(ao2, ro.z, x);  fma4(ao3, ro.w, x);
        fma4(ai0, ri.x, x);  fma4(ai1, ri.y, x);
        fma4(ai2, ri.z, x);  fma4(ai3, ri.w, x);
    }

    const int eb = e4 * 4;
    flush_nz(ao0, eb + 0, 0);  flush_nz(ai0, eb + 0, 1);
    flush_nz(ao1, eb + 1, 0);  flush_nz(ai1, eb + 1, 1);
    flush_nz(ao2, eb + 2, 0);  flush_nz(ai2, eb + 2, 1);
    flush_nz(ao3, eb + 3, 0);  flush_nz(ai3, eb + 3, 1);
}

__global__ __launch_bounds__(M_THREADS)
void edgenet_mlp_kernel(const float* __restrict__ W1,
                        const float* __restrict__ b1,
                        const float* __restrict__ W2,
                        const float* __restrict__ b2,
                        float* __restrict__ out)
{
    __shared__ __align__(16) float sW1t[NHID][8];   // W1 transposed [j][k]
    __shared__ float sb1[NHID];
    __shared__ float sW2[NHID];

    const int tid  = threadIdx.x;
    const int lane = tid & 31;
    const int w    = tid >> 5;
    const int sub  = lane & 7;                       // 0..7: hidden-unit slice
    // Warp handles 4 edges: lanes (8q+sub) share edge e_base+q.
    const int e    = (blockIdx.x * (M_THREADS >> 5) + w) * 4 + (lane >> 3);

    // Prefetch this edge's 8 accumulated features (L2-hot, 8-lane bcast).
    const float4* acc4 = (const float4*)&g_accum[(size_t)e * 8];
    float4 bo = __ldg(&acc4[0]);
    float4 bi = __ldg(&acc4[1]);

    // Weight staging overlaps the loads above.
    for (int i = tid; i < 8 * NHID; i += M_THREADS) {
        int k = i / NHID, j = i % NHID;              // W1 is [8,100] row-major
        sW1t[j][k] = W1[i];
    }
    for (int i = tid; i < NHID; i += M_THREADS) {
        sb1[i] = b1[i];
        sW2[i] = W2[i];
    }
    __syncthreads();

    // MLP split: sub<4 -> 13 units at 13*sub; sub>=4 -> 12 units at 12*sub+4.
    const int start = (sub < 4) ? 13 * sub : 12 * sub + 4;
    const int len   = (sub < 4) ? 13 : 12;
    float acc = 0.0f;
    #pragma unroll
    for (int k = 0; k < 13; ++k) {
        if (k < len) {
            const int j = start + k;
            const float4 w0 = *(const float4*)&sW1t[j][0];
            const float4 w1 = *(const float4*)&sW1t[j][4];
            float s = sb1[j];
            s = fmaf(bo.x, w0.x, s);
            s = fmaf(bo.y, w0.y, s);
            s = fmaf(bo.z, w0.z, s);
            s = fmaf(bo.w, w0.w, s);
            s = fmaf(bi.x, w1.x, s);
            s = fmaf(bi.y, w1.y, s);
            s = fmaf(bi.z, w1.z, s);
            s = fmaf(bi.w, w1.w, s);
            acc = fmaf(fast_tanh(s), sW2[j], acc);
        }
    }
    // Combine across the 8 sub-lanes of this edge.
    acc += __shfl_xor_sync(0xFFFFFFFF, acc, 1);
    acc += __shfl_xor_sync(0xFFFFFFFF, acc, 2);
    acc += __shfl_xor_sync(0xFFFFFFFF, acc, 4);

    if (sub == 0) {
        float a = acc + __ldg(b2);
        out[e] = __fdividef(1.0f, 1.0f + __expf(-a));
        // Re-zero this edge's accumulator for the next graph replay (all
        // sub-lanes consumed their loads before the shuffles above).
        float4* z = (float4*)&g_accum[(size_t)e * 8];
        z[0] = make_float4(0.f, 0.f, 0.f, 0.f);
        z[1] = make_float4(0.f, 0.f, 0.f, 0.f);
    }
}

extern "C" void kernel_launch(void* const* d_in, const int* in_sizes, int n_in,
                              void* d_out, int out_size)
{
    // metadata order: X, Ri, Ro, W1, b1, W2, b2
    const float* X  = (const float*)d_in[0];
    const float* Ri = (const float*)d_in[1];
    const float* Ro = (const float*)d_in[2];
    const float* W1 = (const float*)d_in[3];
    const float* b1 = (const float*)d_in[4];
    const float* W2 = (const float*)d_in[5];
    const float* b2 = (const float*)d_in[6];
    float* out = (float*)d_out;

    dim3 grid1(EGRPS, S_SEG);              // 32 x 16 = 512 blocks of 256 thr
    edgenet_accum_kernel<<<grid1, A_THREADS>>>(X, Ri, Ro);

    // warp = 4 edges -> 32768 / (8 warps * 4) = 1024 blocks
    dim3 grid2(N_EDGES / ((M_THREADS >> 5) * 4));
    edgenet_mlp_kernel<<<grid2, M_THREADS>>>(W1, b1, W2, b2, out);
}

// round 12
// speedup vs baseline: 1.0396x; 1.0396x over previous
#include <cuda_runtime.h>

// EdgeNet v12: R10 architecture (best, 308.8us) + PDL overlap.
// Phase-1: 512 blocks stream Ro/Ri at 7.19 TB/s, flush only nonzero segment
// partials via atomicAdd into 1 MB accumulator, then signal dependents.
// Phase-2 (PDL): launches under phase-1's tail, stages MLP weights early,
// griddepcontrol.wait, then reads L2-hot accum and runs the MLP.

#define N_NODES 8192
#define N_EDGES 32768
#define S_SEG   16
#define NODES_PER_SEG (N_NODES / S_SEG)      // 512
#define E4      (N_EDGES / 4)                // 8192 float4 columns
#define A_THREADS 256
#define EGRPS   (E4 / A_THREADS)             // 32 edge-group blocks
#define NHID    100
#define M_THREADS 256

// Direct accumulator: [edge][8] floats (bo.xyzw, bi.xyzw).  1 MB.
// BSS zero-init covers run 1; phase-2 re-zeroes after consuming.
__device__ float g_accum[(size_t)N_EDGES * 8];

__device__ __forceinline__ void fma4(float4& a, float s, const float4& x) {
    a.x = fmaf(s, x.x, a.x);
    a.y = fmaf(s, x.y, a.y);
    a.z = fmaf(s, x.z, a.z);
    a.w = fmaf(s, x.w, a.w);
}
__device__ __forceinline__ float fast_tanh(float x) {
    float e = __expf(2.0f * x);
    return 1.0f - __fdividef(2.0f, e + 1.0f);
}

__device__ __forceinline__ void flush_nz(const float4& v, int e, int half) {
    // Skip all-zero partials (exact: each (edge,side) has exactly one nonzero
    // segment, landing on a zeroed slot).
    if (v.x != 0.0f || v.y != 0.0f || v.z != 0.0f || v.w != 0.0f) {
        float* a = &g_accum[(size_t)e * 8 + half * 4];
        atomicAdd(a + 0, v.x);
        atomicAdd(a + 1, v.y);
        atomicAdd(a + 2, v.z);
        atomicAdd(a + 3, v.w);
    }
}

__global__ __launch_bounds__(A_THREADS, 4)
void edgenet_accum_kernel(const float* __restrict__ X,
                          const float* __restrict__ Ri,
                          const float* __restrict__ Ro)
{
    __shared__ float4 sX[NODES_PER_SEG];   // 8 KB

    const int tid = threadIdx.x;
    const int seg = blockIdx.y;
    const int n0  = seg * NODES_PER_SEG;

    const float4* __restrict__ X4 = (const float4*)X;
    for (int i = tid; i < NODES_PER_SEG; i += A_THREADS)
        sX[i] = X4[n0 + i];
    __syncthreads();

    const int e4 = blockIdx.x * A_THREADS + tid;
    const float4* __restrict__ ro_p = (const float4*)Ro + (size_t)n0 * E4 + e4;
    const float4* __restrict__ ri_p = (const float4*)Ri + (size_t)n0 * E4 + e4;

    float4 ao0 = {0,0,0,0}, ao1 = {0,0,0,0}, ao2 = {0,0,0,0}, ao3 = {0,0,0,0};
    float4 ai0 = {0,0,0,0}, ai1 = {0,0,0,0}, ai2 = {0,0,0,0}, ai3 = {0,0,0,0};

    #pragma unroll 4
    for (int n = 0; n < NODES_PER_SEG; ++n) {
        const float4 ro = __ldcs(&ro_p[(size_t)n * E4]);   // stream-once
        const float4 ri = __ldcs(&ri_p[(size_t)n * E4]);
        const float4 x  = sX[n];
        fma4(ao0, ro.x, x);  fma4(ao1, ro.y, x);
        fma4(ao2, ro.z, x);  fma4(ao3, ro.w, x);
        fma4(ai0, ri.x, x);  fma4(ai1, ri.y, x);
        fma4(ai2, ri.z, x);  fma4(ai3, ri.w, x);
    }

    const int eb = e4 * 4;
    flush_nz(ao0, eb + 0, 0);  flush_nz(ai0, eb + 0, 1);
    flush_nz(ao1, eb + 1, 0);  flush_nz(ai1, eb + 1, 1);
    flush_nz(ao2, eb + 2, 0);  flush_nz(ai2, eb + 2, 1);
    flush_nz(ao3, eb + 3, 0);  flush_nz(ai3, eb + 3, 1);

    // All of this block's accum writes are done -> allow dependent grid.
    asm volatile("griddepcontrol.launch_dependents;" ::: "memory");
}

__global__ __launch_bounds__(M_THREADS)
void edgenet_mlp_kernel(const float* __restrict__ W1,
                        const float* __restrict__ b1,
                        const float* __restrict__ W2,
                        const float* __restrict__ b2,
                        float* __restrict__ out)
{
    __shared__ __align__(16) float sW1t[NHID][8];   // W1 transposed [j][k]
    __shared__ float sb1[NHID];
    __shared__ float sW2[NHID];

    const int tid  = threadIdx.x;
    const int lane = tid & 31;
    const int w    = tid >> 5;
    const int sub  = lane & 3;                       // hidden-unit quarter
    // Warp handles 8 edges: lanes (4q+sub) share edge e_base+q.
    const int e    = (blockIdx.x * (M_THREADS >> 5) + w) * 8 + (lane >> 2);

    // ---- Prologue (overlaps phase-1 tail under PDL): stage weights ----
    for (int i = tid; i < 8 * NHID; i += M_THREADS) {
        int k = i / NHID, j = i % NHID;              // W1 is [8,100] row-major
        sW1t[j][k] = W1[i];
    }
    for (int i = tid; i < NHID; i += M_THREADS) {
        sb1[i] = b1[i];
        sW2[i] = W2[i];
    }
    const float bias2 = __ldg(b2);
    __syncthreads();

    // ---- Dependency: accum must be complete before we read it ----
    asm volatile("griddepcontrol.wait;" ::: "memory");

    const float4* acc4 = (const float4*)&g_accum[(size_t)e * 8];
    float4 bo = acc4[0];
    float4 bi = acc4[1];

    // Each sub-lane computes 25 hidden units.
    float acc = 0.0f;
    const int jbase = sub * (NHID / 4);
    #pragma unroll 5
    for (int k = 0; k < NHID / 4; ++k) {
        const int j = jbase + k;
        const float4 w0 = *(const float4*)&sW1t[j][0];
        const float4 w1 = *(const float4*)&sW1t[j][4];
        float s = sb1[j];
        s = fmaf(bo.x, w0.x, s);
        s = fmaf(bo.y, w0.y, s);
        s = fmaf(bo.z, w0.z, s);
        s = fmaf(bo.w, w0.w, s);
        s = fmaf(bi.x, w1.x, s);
        s = fmaf(bi.y, w1.y, s);
        s = fmaf(bi.z, w1.z, s);
        s = fmaf(bi.w, w1.w, s);
        acc = fmaf(fast_tanh(s), sW2[j], acc);
    }
    acc += __shfl_xor_sync(0xFFFFFFFF, acc, 1);
    acc += __shfl_xor_sync(0xFFFFFFFF, acc, 2);

    if (sub == 0) {
        float a = acc + bias2;
        out[e] = __fdividef(1.0f, 1.0f + __expf(-a));
        // Re-zero this edge's accumulator for the next graph replay (all
        // sub-lanes consumed their loads before the shuffles above).
        float4* z = (float4*)&g_accum[(size_t)e * 8];
        z[0] = make_float4(0.f, 0.f, 0.f, 0.f);
        z[1] = make_float4(0.f, 0.f, 0.f, 0.f);
    }
}

extern "C" void kernel_launch(void* const* d_in, const int* in_sizes, int n_in,
                              void* d_out, int out_size)
{
    // metadata order: X, Ri, Ro, W1, b1, W2, b2
    const float* X  = (const float*)d_in[0];
    const float* Ri = (const float*)d_in[1];
    const float* Ro = (const float*)d_in[2];
    const float* W1 = (const float*)d_in[3];
    const float* b1 = (const float*)d_in[4];
    const float* W2 = (const float*)d_in[5];
    const float* b2 = (const float*)d_in[6];
    float* out = (float*)d_out;

    dim3 grid1(EGRPS, S_SEG);              // 32 x 16 = 512 blocks of 256 thr
    edgenet_accum_kernel<<<grid1, A_THREADS>>>(X, Ri, Ro);

    // Phase-2 with programmatic dependent launch: prologue overlaps phase-1.
    cudaLaunchConfig_t cfg = {};
    cfg.gridDim  = dim3(N_EDGES / ((M_THREADS >> 5) * 8));   // 512 blocks
    cfg.blockDim = dim3(M_THREADS);
    cfg.dynamicSmemBytes = 0;
    cfg.stream = 0;
    cudaLaunchAttribute attrs[1];
    attrs[0].id = cudaLaunchAttributeProgrammaticStreamSerialization;
    attrs[0].val.programmaticStreamSerializationAllowed = 1;
    cfg.attrs = attrs;
    cfg.numAttrs = 1;
    cudaLaunchKernelEx(&cfg, edgenet_mlp_kernel, W1, b1, W2, b2, out);
}